// round 12
// baseline (speedup 1.0000x reference)
#include <cuda_runtime.h>
#include <cuda_bf16.h>

// PositionalEncoding: out[p][j] = X[p][j] + (j even ? sin(p*w_j) : cos(p*w_j))
//   w_j = 10000^{-(j + (j%2))/n},  n = 4096, m = 8192 rows.
//
// R12 (convergence): R11 structure — float4, ROWS=8 batch-loaded, 3-state
// shared-frequency angle-addition recurrence, per-CTA L2 policy split,
// streaming stores — with TPB=256 (grid 4096 CTAs) to halve CTA-scheduling
// events. Kernel is at the mixed read/write HBM ceiling (~7.2 TB/s effective,
// ~91% of spec); all other levers measured neutral over R5-R11.

#define PE_M     8192
#define PE_N     4096
#define PE_NV4   (PE_N / 4)      // 1024 float4 per row
#define PE_ROWS  8               // rows per thread (batch-loaded)
#define PE_TPB   256             // threads per block (column-quads)
#define PE_PERSIST_ROWS 6144

__device__ __forceinline__ float4 ldg_pol(const float4* p, unsigned long long pol) {
    float4 v;
    asm volatile("ld.global.nc.L2::cache_hint.v4.f32 {%0,%1,%2,%3}, [%4], %5;"
                 : "=f"(v.x), "=f"(v.y), "=f"(v.z), "=f"(v.w)
                 : "l"(p), "l"(pol));
    return v;
}

__global__ __launch_bounds__(PE_TPB)
void pe_kernel(const float4* __restrict__ X, float4* __restrict__ Out) {
    const int cv   = blockIdx.x * PE_TPB + threadIdx.x;  // column-quad index, 0..1023
    const int row0 = blockIdx.y * PE_ROWS;

    unsigned long long pol;
    if (row0 < PE_PERSIST_ROWS) {
        asm volatile("createpolicy.fractional.L2::evict_last.b64 %0, 1.0;" : "=l"(pol));
    } else {
        asm volatile("createpolicy.fractional.L2::evict_first.b64 %0, 1.0;" : "=l"(pol));
    }

    const float L2_10K = 13.287712379549449f;  // log2(10000)

    // 3 distinct frequencies per quad: exponents (4cv + 2t)/n, t = 0,1,2
    float s[3], c[3], sw[3], cw[3];
#pragma unroll
    for (int t = 0; t < 3; t++) {
        const float e = (float)(4 * cv + 2 * t) * (1.0f / (float)PE_N);
        const float w = exp2f(-e * L2_10K);           // 10000^{-e}
        sincosf((float)row0 * w, &s[t], &c[t]);       // precise: angle up to ~8191
        __sincosf(w, &sw[t], &cw[t]);                 // fast: w in (0, 1]
    }

    const float4* __restrict__ xp = X   + (size_t)row0 * PE_NV4 + cv;
    float4*       __restrict__ yp = Out + (size_t)row0 * PE_NV4 + cv;

    // Batch loads (ptxas pipelines these against the recurrence)
    float4 v[PE_ROWS];
#pragma unroll
    for (int r = 0; r < PE_ROWS; r++)
        v[r] = ldg_pol(xp + (size_t)r * PE_NV4, pol);

    // Recurrence + add
#pragma unroll
    for (int r = 0; r < PE_ROWS; r++) {
        v[r].x += s[0];
        v[r].y += c[1];
        v[r].z += s[1];
        v[r].w += c[2];
#pragma unroll
        for (int t = 0; t < 3; t++) {
            const float ns = fmaf(s[t], cw[t],  c[t] * sw[t]);
            const float nc = fmaf(c[t], cw[t], -s[t] * sw[t]);
            s[t] = ns; c[t] = nc;
        }
    }

    // Streaming stores
#pragma unroll
    for (int r = 0; r < PE_ROWS; r++)
        __stcs(yp + (size_t)r * PE_NV4, v[r]);
}

extern "C" void kernel_launch(void* const* d_in, const int* in_sizes, int n_in,
                              void* d_out, int out_size) {
    (void)in_sizes; (void)n_in; (void)out_size;
    const float4* X   = (const float4*)d_in[0];
    float4*       Out = (float4*)d_out;

    dim3 block(PE_TPB);
    dim3 grid(PE_NV4 / PE_TPB, PE_M / PE_ROWS);   // (4, 1024) = 4096 CTAs
    pe_kernel<<<grid, block>>>(X, Out);
}

// round 13
// speedup vs baseline: 1.0164x; 1.0164x over previous
#include <cuda_runtime.h>
#include <cuda_bf16.h>

// PositionalEncoding: out[p][j] = X[p][j] + (j even ? sin(p*w_j) : cos(p*w_j))
//   w_j = 10000^{-(j + (j%2))/n},  n = 4096, m = 8192 rows.
//
// FINAL (R13, converged): pure HBM-bound elementwise stream at ~7.25 TB/s
// effective (~91% of 8 TB/s spec). Transcendentals amortized away via the
// angle-addition recurrence along rows:
//   s' = s*cos(w) + c*sin(w),  c' = c*cos(w) - s*sin(w)
// with shared-frequency compression: cols 4cv+{0,1,2,3} have exponents
// (4cv+{0,2,2,4})/n -> only 3 distinct frequencies -> 3 states/thread,
// 6 sincos per 32 elements. Streaming loads/stores (zero reuse).
// Measured plateau (R5-R12): occupancy, vector width, L2 policy, unroll and
// phase structure all neutral; this is the cleanest point on that plateau.

#define PE_M     8192
#define PE_N     4096
#define PE_NV4   (PE_N / 4)      // 1024 float4 per row
#define PE_ROWS  8               // rows per thread (batch-loaded)
#define PE_TPB   256             // threads per block (column-quads)

__global__ __launch_bounds__(PE_TPB)
void pe_kernel(const float4* __restrict__ X, float4* __restrict__ Out) {
    const int cv   = blockIdx.x * PE_TPB + threadIdx.x;  // column-quad index, 0..1023
    const int row0 = blockIdx.y * PE_ROWS;

    const float L2_10K = 13.287712379549449f;  // log2(10000)

    // 3 distinct frequencies per quad: exponents (4cv + 2t)/n, t = 0,1,2
    float s[3], c[3], sw[3], cw[3];
#pragma unroll
    for (int t = 0; t < 3; t++) {
        const float e = (float)(4 * cv + 2 * t) * (1.0f / (float)PE_N);
        const float w = exp2f(-e * L2_10K);           // 10000^{-e}
        sincosf((float)row0 * w, &s[t], &c[t]);       // precise: angle up to ~8191
        __sincosf(w, &sw[t], &cw[t]);                 // fast: w in (0, 1]
    }

    const float4* __restrict__ xp = X   + (size_t)row0 * PE_NV4 + cv;
    float4*       __restrict__ yp = Out + (size_t)row0 * PE_NV4 + cv;

    // Batch loads — ptxas pipelines these against the recurrence below.
    float4 v[PE_ROWS];
#pragma unroll
    for (int r = 0; r < PE_ROWS; r++)
        v[r] = __ldcs(xp + (size_t)r * PE_NV4);

    // Add table values; advance rotation per row.
    // cols 4cv+{0,1,2,3}: sin(w0), cos(w1), sin(w1), cos(w2)
#pragma unroll
    for (int r = 0; r < PE_ROWS; r++) {
        v[r].x += s[0];
        v[r].y += c[1];
        v[r].z += s[1];
        v[r].w += c[2];
#pragma unroll
        for (int t = 0; t < 3; t++) {
            const float ns = fmaf(s[t], cw[t],  c[t] * sw[t]);
            const float nc = fmaf(c[t], cw[t], -s[t] * sw[t]);
            s[t] = ns; c[t] = nc;
        }
    }

    // Streaming stores (write-once, evict-first).
#pragma unroll
    for (int r = 0; r < PE_ROWS; r++)
        __stcs(yp + (size_t)r * PE_NV4, v[r]);
}

extern "C" void kernel_launch(void* const* d_in, const int* in_sizes, int n_in,
                              void* d_out, int out_size) {
    (void)in_sizes; (void)n_in; (void)out_size;
    const float4* X   = (const float4*)d_in[0];
    float4*       Out = (float4*)d_out;

    dim3 block(PE_TPB);
    dim3 grid(PE_NV4 / PE_TPB, PE_M / PE_ROWS);   // (4, 1024) = 4096 CTAs
    pe_kernel<<<grid, block>>>(X, Out);
}

// round 14
// speedup vs baseline: 1.0216x; 1.0050x over previous
#include <cuda_runtime.h>
#include <cuda_bf16.h>

// PositionalEncoding: out[p][j] = X[p][j] + (j even ? sin(p*w_j) : cos(p*w_j))
//   w_j = 10000^{-(j + (j%2))/n},  n = 4096, m = 8192 rows.
//
// R14: R13 discovered that true register-resident load batching (regs=60,
// MLP=8/thread) at occ ~41% beats shallow-MLP high-occupancy variants.
// Push the axis: ROWS=16 batch-loaded (16 LDG.128 in flight per thread,
// ~88 regs, occ ~31%). TPB=128, grid (8,512)=4096 CTAs for wave backfill.
// 3-state shared-frequency angle-addition recurrence as before.

#define PE_M     8192
#define PE_N     4096
#define PE_NV4   (PE_N / 4)      // 1024 float4 per row
#define PE_ROWS  16              // rows per thread (all batch-loaded)
#define PE_TPB   128             // threads per block (column-quads)

__global__ __launch_bounds__(PE_TPB)
void pe_kernel(const float4* __restrict__ X, float4* __restrict__ Out) {
    const int cv   = blockIdx.x * PE_TPB + threadIdx.x;  // column-quad index, 0..1023
    const int row0 = blockIdx.y * PE_ROWS;

    const float L2_10K = 13.287712379549449f;  // log2(10000)

    // 3 distinct frequencies per quad: exponents (4cv + 2t)/n, t = 0,1,2
    float s[3], c[3], sw[3], cw[3];
#pragma unroll
    for (int t = 0; t < 3; t++) {
        const float e = (float)(4 * cv + 2 * t) * (1.0f / (float)PE_N);
        const float w = exp2f(-e * L2_10K);           // 10000^{-e}
        sincosf((float)row0 * w, &s[t], &c[t]);       // precise: angle up to ~8191
        __sincosf(w, &sw[t], &cw[t]);                 // fast: w in (0, 1]
    }

    const float4* __restrict__ xp = X   + (size_t)row0 * PE_NV4 + cv;
    float4*       __restrict__ yp = Out + (size_t)row0 * PE_NV4 + cv;

    // Batch all 16 loads — register-resident, maximal per-thread MLP.
    float4 v[PE_ROWS];
#pragma unroll
    for (int r = 0; r < PE_ROWS; r++)
        v[r] = __ldcs(xp + (size_t)r * PE_NV4);

    // Add table values; advance rotation per row.
    // cols 4cv+{0,1,2,3}: sin(w0), cos(w1), sin(w1), cos(w2)
#pragma unroll
    for (int r = 0; r < PE_ROWS; r++) {
        v[r].x += s[0];
        v[r].y += c[1];
        v[r].z += s[1];
        v[r].w += c[2];
#pragma unroll
        for (int t = 0; t < 3; t++) {
            const float ns = fmaf(s[t], cw[t],  c[t] * sw[t]);
            const float nc = fmaf(c[t], cw[t], -s[t] * sw[t]);
            s[t] = ns; c[t] = nc;
        }
    }

    // Streaming stores (write-once, evict-first).
#pragma unroll
    for (int r = 0; r < PE_ROWS; r++)
        __stcs(yp + (size_t)r * PE_NV4, v[r]);
}

extern "C" void kernel_launch(void* const* d_in, const int* in_sizes, int n_in,
                              void* d_out, int out_size) {
    (void)in_sizes; (void)n_in; (void)out_size;
    const float4* X   = (const float4*)d_in[0];
    float4*       Out = (float4*)d_out;

    dim3 block(PE_TPB);
    dim3 grid(PE_NV4 / PE_TPB, PE_M / PE_ROWS);   // (8, 512) = 4096 CTAs
    pe_kernel<<<grid, block>>>(X, Out);
}